// round 6
// baseline (speedup 1.0000x reference)
#include <cuda_runtime.h>
#include <cuda_bf16.h>

#define N_NODES 65536
#define N_EDGES 1048576
#define IN_F    64
#define OUT_F   64

#define SCAN_BLOCKS 256
#define SCAN_CHUNK  256   // N_NODES / SCAN_BLOCKS

// -------- device-global scratch (allocation-free) --------
__device__ float g_support[(size_t)N_NODES * OUT_F];   // 16 MB, X @ W
__device__ int   g_cnt[N_NODES];                       // per-row edge counts
__device__ int   g_rowptr[N_NODES + 1];                // CSR row pointers
__device__ int   g_cursor[N_NODES];                    // scatter cursors
__device__ int2  g_edge[N_EDGES];                      // packed (col, val-bits)
__device__ int   g_bsum[SCAN_BLOCKS];                  // per-block sums
__device__ int   g_boff[SCAN_BLOCKS];                  // per-block offsets

// ---------------------------------------------------------
// Kernel 1: support = X @ W   (tiled, W + X-tile in shared)
// ---------------------------------------------------------
__global__ void __launch_bounds__(256) gemm_kernel(const float* __restrict__ X,
                                                   const float* __restrict__ W)
{
    __shared__ float sW[IN_F * OUT_F];   // 16 KB
    __shared__ float sX[32 * IN_F];      // 8 KB

    const int tid = threadIdx.x;
    const int rowBase = blockIdx.x * 32;

    for (int i = tid; i < IN_F * OUT_F / 4; i += 256)
        ((float4*)sW)[i] = ((const float4*)W)[i];
    for (int i = tid; i < 32 * IN_F / 4; i += 256)
        ((float4*)sX)[i] = ((const float4*)(X + (size_t)rowBase * IN_F))[i];
    __syncthreads();

    const int r   = tid >> 3;
    const int sub = tid & 7;

    float acc[8];
#pragma unroll
    for (int j = 0; j < 8; j++) acc[j] = 0.f;

#pragma unroll 8
    for (int k = 0; k < IN_F; k++) {
        const float xv = sX[r * IN_F + k];
#pragma unroll
        for (int j = 0; j < 8; j++)
            acc[j] += xv * sW[k * OUT_F + 8 * sub + j];
    }

    float* out = g_support + ((size_t)(rowBase + r) * OUT_F + 8 * sub);
    float4 o0 = {acc[0], acc[1], acc[2], acc[3]};
    float4 o1 = {acc[4], acc[5], acc[6], acc[7]};
    *(float4*)(out)     = o0;
    *(float4*)(out + 4) = o1;
}

// ---------------------------------------------------------
// Kernel 2: zero histogram counters (vectorized)
// ---------------------------------------------------------
__global__ void zero_cnt_kernel()
{
    int i = blockIdx.x * blockDim.x + threadIdx.x;
    if (i < N_NODES / 4) ((int4*)g_cnt)[i] = make_int4(0, 0, 0, 0);
}

// ---------------------------------------------------------
// Kernel 3: histogram of destination rows
// ---------------------------------------------------------
__global__ void hist_kernel(const int* __restrict__ rows)
{
    int e = blockIdx.x * blockDim.x + threadIdx.x;
    if (e < N_EDGES) atomicAdd(&g_cnt[rows[e]], 1);
}

// ---------------------------------------------------------
// Kernel 4a: per-block reduction of counts
// ---------------------------------------------------------
__global__ void __launch_bounds__(256) block_reduce_kernel()
{
    __shared__ int sh[8];
    const int t = threadIdx.x;
    int v = g_cnt[blockIdx.x * SCAN_CHUNK + t];

#pragma unroll
    for (int off = 16; off > 0; off >>= 1)
        v += __shfl_down_sync(0xffffffff, v, off);
    if ((t & 31) == 0) sh[t >> 5] = v;
    __syncthreads();
    if (t < 8) {
        int s = sh[t];
#pragma unroll
        for (int off = 4; off > 0; off >>= 1)
            s += __shfl_down_sync(0xff, s, off);
        if (t == 0) g_bsum[blockIdx.x] = s;
    }
}

// ---------------------------------------------------------
// Kernel 4b: exclusive scan of the 256 block sums (1 block)
// ---------------------------------------------------------
__global__ void __launch_bounds__(256) scan_bsum_kernel()
{
    __shared__ int sh[256];
    const int t = threadIdx.x;
    int v = g_bsum[t];
    sh[t] = v;
    __syncthreads();
#pragma unroll
    for (int off = 1; off < 256; off <<= 1) {
        int u = (t >= off) ? sh[t - off] : 0;
        __syncthreads();
        sh[t] += u;
        __syncthreads();
    }
    g_boff[t] = sh[t] - v;
    if (t == 255) g_rowptr[N_NODES] = sh[255];
}

// ---------------------------------------------------------
// Kernel 4c: per-block exclusive scan + offset -> rowptr, cursor
// ---------------------------------------------------------
__global__ void __launch_bounds__(256) block_scan_kernel()
{
    __shared__ int sh[256];
    const int t = threadIdx.x;
    const int gi = blockIdx.x * SCAN_CHUNK + t;
    const int v = g_cnt[gi];
    sh[t] = v;
    __syncthreads();
#pragma unroll
    for (int off = 1; off < 256; off <<= 1) {
        int u = (t >= off) ? sh[t - off] : 0;
        __syncthreads();
        sh[t] += u;
        __syncthreads();
    }
    const int p = g_boff[blockIdx.x] + sh[t] - v;
    g_rowptr[gi] = p;
    g_cursor[gi] = p;
}

// ---------------------------------------------------------
// Kernel 5: scatter COO edges into CSR order (packed 8B store)
// ---------------------------------------------------------
__global__ void scatter_kernel(const int*   __restrict__ rows,
                               const int*   __restrict__ cols,
                               const float* __restrict__ vals)
{
    int e = blockIdx.x * blockDim.x + threadIdx.x;
    if (e < N_EDGES) {
        int p = atomicAdd(&g_cursor[rows[e]], 1);
        g_edge[p] = make_int2(cols[e], __float_as_int(vals[e]));
    }
}

// ---------------------------------------------------------
// Kernel 6: CSR SpMM + bias + ReLU
// one warp per row; 4 groups of 8 lanes, one edge slot per group
// (4 edges in flight); each lane owns 8 features (2 x float4 gather).
// ---------------------------------------------------------
__global__ void __launch_bounds__(256) spmm_kernel(const float* __restrict__ bias,
                                                   float*       __restrict__ out)
{
    const int warp = (blockIdx.x * blockDim.x + threadIdx.x) >> 5;
    const int lane = threadIdx.x & 31;
    if (warp >= N_NODES) return;

    const int beg = g_rowptr[warp];
    const int end = g_rowptr[warp + 1];

    const int grp = lane >> 3;          // 0..3 edge slot
    const int fl  = (lane & 7) * 8;     // 8 features per lane

    float4 a0 = {0.f, 0.f, 0.f, 0.f};
    float4 a1 = {0.f, 0.f, 0.f, 0.f};

    for (int i = beg + grp; i < end; i += 4) {
        const int2  e = g_edge[i];
        const float v = __int_as_float(e.y);
        const float4* p = (const float4*)(g_support + (size_t)e.x * OUT_F + fl);
        const float4 s0 = p[0];
        const float4 s1 = p[1];
        a0.x += v * s0.x;  a0.y += v * s0.y;  a0.z += v * s0.z;  a0.w += v * s0.w;
        a1.x += v * s1.x;  a1.y += v * s1.y;  a1.z += v * s1.z;  a1.w += v * s1.w;
    }

    // reduce across the 4 groups (xor 8, then xor 16)
#pragma unroll
    for (int off = 8; off <= 16; off <<= 1) {
        a0.x += __shfl_xor_sync(0xffffffff, a0.x, off);
        a0.y += __shfl_xor_sync(0xffffffff, a0.y, off);
        a0.z += __shfl_xor_sync(0xffffffff, a0.z, off);
        a0.w += __shfl_xor_sync(0xffffffff, a0.w, off);
        a1.x += __shfl_xor_sync(0xffffffff, a1.x, off);
        a1.y += __shfl_xor_sync(0xffffffff, a1.y, off);
        a1.z += __shfl_xor_sync(0xffffffff, a1.z, off);
        a1.w += __shfl_xor_sync(0xffffffff, a1.w, off);
    }

    if (grp == 0) {
        const float4 b0 = *(const float4*)(bias + fl);
        const float4 b1 = *(const float4*)(bias + fl + 4);
        float4 o0, o1;
        o0.x = fmaxf(a0.x + b0.x, 0.f);
        o0.y = fmaxf(a0.y + b0.y, 0.f);
        o0.z = fmaxf(a0.z + b0.z, 0.f);
        o0.w = fmaxf(a0.w + b0.w, 0.f);
        o1.x = fmaxf(a1.x + b1.x, 0.f);
        o1.y = fmaxf(a1.y + b1.y, 0.f);
        o1.z = fmaxf(a1.z + b1.z, 0.f);
        o1.w = fmaxf(a1.w + b1.w, 0.f);
        float* dst = out + (size_t)warp * OUT_F + fl;
        *(float4*)(dst)     = o0;
        *(float4*)(dst + 4) = o1;
    }
}

// ---------------------------------------------------------
// launch
// ---------------------------------------------------------
extern "C" void kernel_launch(void* const* d_in, const int* in_sizes, int n_in,
                              void* d_out, int out_size)
{
    const float* X     = (const float*)d_in[0];
    const int*   erow  = (const int*)  d_in[1];
    const int*   ecol  = (const int*)  d_in[2];
    const float* eval  = (const float*)d_in[3];
    const float* W     = (const float*)d_in[4];
    const float* bias  = (const float*)d_in[5];
    float*       out   = (float*)d_out;

    gemm_kernel<<<N_NODES / 32, 256>>>(X, W);

    zero_cnt_kernel<<<N_NODES / 4 / 256, 256>>>();
    hist_kernel<<<N_EDGES / 256, 256>>>(erow);

    block_reduce_kernel<<<SCAN_BLOCKS, 256>>>();
    scan_bsum_kernel<<<1, 256>>>();
    block_scan_kernel<<<SCAN_BLOCKS, 256>>>();

    scatter_kernel<<<N_EDGES / 256, 256>>>(erow, ecol, eval);

    spmm_kernel<<<N_NODES / 8, 256>>>(bias, out);
}